// round 1
// baseline (speedup 1.0000x reference)
#include <cuda_runtime.h>
#include <cstdint>
#include <cstddef>

#define N_NODES 50000
#define N_EDGES 800000
#define F 128
#define KCAT 256
#define BM 64

// Scratch (static device globals — no allocation)
__device__ float g_hq[(size_t)N_NODES * F];
__device__ float g_agg[(size_t)N_NODES * F];
__device__ float g_wsum[N_NODES];
__device__ float g_winv[N_NODES];

// ---------------------------------------------------------------------------
// Zero the accumulation buffers (must run every replay)
// ---------------------------------------------------------------------------
__global__ void zero_kernel() {
    size_t i = (size_t)blockIdx.x * blockDim.x + threadIdx.x;
    size_t stride = (size_t)gridDim.x * blockDim.x;
    size_t total = (size_t)N_NODES * F;
    for (size_t j = i; j < total; j += stride) g_agg[j] = 0.0f;
    for (size_t j = i; j < N_NODES; j += stride) g_wsum[j] = 0.0f;
}

// ---------------------------------------------------------------------------
// GEMM1: g_hq[N,128] = h[N,128] @ Qw[128,128]^T + Qb
// block: 256 threads, tile 64 rows x 128 cols, per-thread 8x4
// ---------------------------------------------------------------------------
__global__ __launch_bounds__(256) void gemm1_kernel(
    const float* __restrict__ h, const float* __restrict__ Qw,
    const float* __restrict__ Qb)
{
    __shared__ float As[BM][33];
    __shared__ float Bs[F][33];

    const int tid = threadIdx.x;
    const int tx = tid & 31;   // col group (4 cols each) — lane id
    const int ty = tid >> 5;   // row group (8 rows each) — warp id
    const int row0 = blockIdx.x * BM;

    float acc[8][4];
#pragma unroll
    for (int i = 0; i < 8; i++)
#pragma unroll
        for (int j = 0; j < 4; j++) acc[i][j] = 0.0f;

    for (int kc = 0; kc < F; kc += 32) {
        // load A tile: 64x32 floats, coalesced, conflict-free STS (pad 33)
#pragma unroll
        for (int it = 0; it < 8; it++) {
            int q = tid + it * 256;
            int r = q >> 5, k = q & 31;
            int gr = row0 + r;
            As[r][k] = (gr < N_NODES) ? h[(size_t)gr * F + kc + k] : 0.0f;
        }
        // load B tile: 128x32 floats
#pragma unroll
        for (int it = 0; it < 16; it++) {
            int q = tid + it * 256;
            int n = q >> 5, k = q & 31;
            Bs[n][k] = Qw[(size_t)n * F + kc + k];
        }
        __syncthreads();

#pragma unroll
        for (int kk = 0; kk < 32; kk++) {
            float a[8], b[4];
#pragma unroll
            for (int i = 0; i < 8; i++) a[i] = As[ty * 8 + i][kk];
#pragma unroll
            for (int j = 0; j < 4; j++) b[j] = Bs[tx * 4 + j][kk];
#pragma unroll
            for (int i = 0; i < 8; i++)
#pragma unroll
                for (int j = 0; j < 4; j++) acc[i][j] += a[i] * b[j];
        }
        __syncthreads();
    }

    float bias[4];
#pragma unroll
    for (int j = 0; j < 4; j++) bias[j] = Qb[tx * 4 + j];

#pragma unroll
    for (int i = 0; i < 8; i++) {
        int gr = row0 + ty * 8 + i;
        if (gr < N_NODES) {
            float4 o;
            o.x = acc[i][0] + bias[0];
            o.y = acc[i][1] + bias[1];
            o.z = acc[i][2] + bias[2];
            o.w = acc[i][3] + bias[3];
            *reinterpret_cast<float4*>(&g_hq[(size_t)gr * F + tx * 4]) = o;
        }
    }
}

// ---------------------------------------------------------------------------
// Edge scatter: one warp per edge, vector f32 reductions into g_agg
// ---------------------------------------------------------------------------
__global__ __launch_bounds__(256) void scatter_kernel(
    const int* __restrict__ src, const int* __restrict__ dst,
    const float* __restrict__ w)
{
    int gwarp = (blockIdx.x * blockDim.x + threadIdx.x) >> 5;
    int lane = threadIdx.x & 31;
    int nwarps = (gridDim.x * blockDim.x) >> 5;

    for (int e = gwarp; e < N_EDGES; e += nwarps) {
        int s = src[e];
        int d = dst[e];
        float we = w[e];
        float4 v = *reinterpret_cast<const float4*>(&g_hq[(size_t)s * F + lane * 4]);
        v.x *= we; v.y *= we; v.z *= we; v.w *= we;
        float* p = &g_agg[(size_t)d * F + lane * 4];
        asm volatile("red.global.add.v4.f32 [%0], {%1, %2, %3, %4};"
                     :: "l"(p), "f"(v.x), "f"(v.y), "f"(v.z), "f"(v.w)
                     : "memory");
        if (lane == 0) atomicAdd(&g_wsum[d], we);
    }
}

// ---------------------------------------------------------------------------
// inv-weight (safediv semantics: w==0 -> 1)
// ---------------------------------------------------------------------------
__global__ void invw_kernel() {
    int i = blockIdx.x * blockDim.x + threadIdx.x;
    if (i < N_NODES) {
        float w = g_wsum[i];
        g_winv[i] = (w == 0.0f) ? 1.0f : 1.0f / w;
    }
}

// ---------------------------------------------------------------------------
// GEMM2: out = l2norm(leaky(concat[h, agg*winv] @ Ww[128,256]^T + Wb))
// ---------------------------------------------------------------------------
__global__ __launch_bounds__(256) void gemm2_kernel(
    const float* __restrict__ h, const float* __restrict__ Ww,
    const float* __restrict__ Wb, float* __restrict__ out)
{
    __shared__ float As[BM][33];
    __shared__ float Bs[F][33];

    const int tid = threadIdx.x;
    const int tx = tid & 31;
    const int ty = tid >> 5;
    const int row0 = blockIdx.x * BM;

    float acc[8][4];
#pragma unroll
    for (int i = 0; i < 8; i++)
#pragma unroll
        for (int j = 0; j < 4; j++) acc[i][j] = 0.0f;

    for (int kc = 0; kc < KCAT; kc += 32) {
        const bool second = (kc >= F);
#pragma unroll
        for (int it = 0; it < 8; it++) {
            int q = tid + it * 256;
            int r = q >> 5, k = q & 31;
            int gr = row0 + r;
            float v = 0.0f;
            if (gr < N_NODES) {
                if (!second) {
                    v = h[(size_t)gr * F + kc + k];
                } else {
                    v = g_agg[(size_t)gr * F + (kc - F) + k] * g_winv[gr];
                }
            }
            As[r][k] = v;
        }
#pragma unroll
        for (int it = 0; it < 16; it++) {
            int q = tid + it * 256;
            int n = q >> 5, k = q & 31;
            Bs[n][k] = Ww[(size_t)n * KCAT + kc + k];
        }
        __syncthreads();

#pragma unroll
        for (int kk = 0; kk < 32; kk++) {
            float a[8], b[4];
#pragma unroll
            for (int i = 0; i < 8; i++) a[i] = As[ty * 8 + i][kk];
#pragma unroll
            for (int j = 0; j < 4; j++) b[j] = Bs[tx * 4 + j][kk];
#pragma unroll
            for (int i = 0; i < 8; i++)
#pragma unroll
                for (int j = 0; j < 4; j++) acc[i][j] += a[i] * b[j];
        }
        __syncthreads();
    }

    float bias[4];
#pragma unroll
    for (int j = 0; j < 4; j++) bias[j] = Wb[tx * 4 + j];

    // leaky relu + row sum-of-squares (warp == row group, lanes cover 128 cols)
    float vout[8][4];
    float sq[8];
#pragma unroll
    for (int i = 0; i < 8; i++) {
        sq[i] = 0.0f;
#pragma unroll
        for (int j = 0; j < 4; j++) {
            float v = acc[i][j] + bias[j];
            v = (v > 0.0f) ? v : 0.01f * v;
            vout[i][j] = v;
            sq[i] += v * v;
        }
    }
#pragma unroll
    for (int i = 0; i < 8; i++) {
#pragma unroll
        for (int off = 16; off > 0; off >>= 1)
            sq[i] += __shfl_xor_sync(0xffffffffu, sq[i], off);
    }

#pragma unroll
    for (int i = 0; i < 8; i++) {
        int gr = row0 + ty * 8 + i;
        if (gr < N_NODES) {
            float nrm = sqrtf(sq[i]);
            float inv = (nrm == 0.0f) ? 1.0f : 1.0f / nrm;
            float4 o;
            o.x = vout[i][0] * inv;
            o.y = vout[i][1] * inv;
            o.z = vout[i][2] * inv;
            o.w = vout[i][3] * inv;
            *reinterpret_cast<float4*>(&out[(size_t)gr * F + tx * 4]) = o;
        }
    }
}

// ---------------------------------------------------------------------------
// Launch
// Inputs: 0:h 1:ppr_weight 2:Qw 3:Qb 4:Ww 5:Wb 6:src 7:dst
// ---------------------------------------------------------------------------
extern "C" void kernel_launch(void* const* d_in, const int* in_sizes, int n_in,
                              void* d_out, int out_size) {
    const float* h   = (const float*)d_in[0];
    const float* ppr = (const float*)d_in[1];
    const float* Qw  = (const float*)d_in[2];
    const float* Qb  = (const float*)d_in[3];
    const float* Ww  = (const float*)d_in[4];
    const float* Wb  = (const float*)d_in[5];
    const int*   src = (const int*)d_in[6];
    const int*   dst = (const int*)d_in[7];
    float* out = (float*)d_out;

    const int gemm_grid = (N_NODES + BM - 1) / BM;  // 782

    zero_kernel<<<1024, 256>>>();
    gemm1_kernel<<<gemm_grid, 256>>>(h, Qw, Qb);
    scatter_kernel<<<2048, 256>>>(src, dst, ppr);
    invw_kernel<<<(N_NODES + 255) / 256, 256>>>();
    gemm2_kernel<<<gemm_grid, 256>>>(h, Ww, Wb, out);
}

// round 2
// speedup vs baseline: 1.4226x; 1.4226x over previous
#include <cuda_runtime.h>
#include <cstdint>
#include <cstddef>

#define N_NODES 50000
#define N_EDGES 800000
#define F 128
#define KCAT 256
#define BM 64
#define NB_SCAN 49   // ceil(50000/1024)

// Scratch (static device globals — no allocation)
__device__ int   g_counts[N_NODES];
__device__ int   g_cursor[N_NODES];
__device__ int   g_offsets[N_NODES + 1];
__device__ int   g_bsum[NB_SCAN];
__device__ int   g_bsumex[NB_SCAN];
__device__ int2  g_pairs[N_EDGES];               // {src, bitcast(weight)} sorted by dst
__device__ float g_aggmean[(size_t)N_NODES * F]; // segsum(w*h[src]) / wsum
__device__ float g_has[N_NODES];                 // 1 if node has incoming edges
__device__ float g_Qc[F * F];                    // Ww2 @ Qw
__device__ float g_qbw[F];                       // Ww2 @ Qb

// ---------------------------------------------------------------------------
// Zero histogram + cursor
// ---------------------------------------------------------------------------
__global__ void zero_kernel() {
    int i = blockIdx.x * blockDim.x + threadIdx.x;
    if (i < N_NODES) { g_counts[i] = 0; g_cursor[i] = 0; }
}

// ---------------------------------------------------------------------------
// Histogram of dst
// ---------------------------------------------------------------------------
__global__ void hist_kernel(const int* __restrict__ dst) {
    int e = blockIdx.x * blockDim.x + threadIdx.x;
    if (e < N_EDGES) atomicAdd(&g_counts[dst[e]], 1);
}

// ---------------------------------------------------------------------------
// Exclusive scan over g_counts -> g_offsets (3 stages)
// ---------------------------------------------------------------------------
__global__ __launch_bounds__(1024) void scanA_kernel() {
    __shared__ int sd[1024];
    int t = threadIdx.x;
    int i = blockIdx.x * 1024 + t;
    int v = (i < N_NODES) ? g_counts[i] : 0;
    sd[t] = v;
    __syncthreads();
    // Hillis-Steele inclusive scan
    for (int off = 1; off < 1024; off <<= 1) {
        int add = (t >= off) ? sd[t - off] : 0;
        __syncthreads();
        sd[t] += add;
        __syncthreads();
    }
    int incl = sd[t];
    if (i < N_NODES) g_offsets[i] = incl - v;  // exclusive, block-local
    if (t == 1023) g_bsum[blockIdx.x] = incl;
}

__global__ void scanB_kernel() {
    if (threadIdx.x == 0) {
        int run = 0;
        for (int b = 0; b < NB_SCAN; b++) {
            g_bsumex[b] = run;
            run += g_bsum[b];
        }
    }
}

__global__ __launch_bounds__(1024) void scanC_kernel() {
    int t = threadIdx.x;
    int i = blockIdx.x * 1024 + t;
    if (i < N_NODES) g_offsets[i] += g_bsumex[blockIdx.x];
    if (blockIdx.x == 0 && t == 0) g_offsets[N_NODES] = N_EDGES;
}

// ---------------------------------------------------------------------------
// Bucket-build: sort (src, w) pairs by dst into CSR order
// ---------------------------------------------------------------------------
__global__ void build_kernel(const int* __restrict__ src, const int* __restrict__ dst,
                             const float* __restrict__ w) {
    int e = blockIdx.x * blockDim.x + threadIdx.x;
    if (e < N_EDGES) {
        int d = dst[e];
        int pos = g_offsets[d] + atomicAdd(&g_cursor[d], 1);
        g_pairs[pos] = make_int2(src[e], __float_as_int(w[e]));
    }
}

// ---------------------------------------------------------------------------
// Qc = Ww2 @ Qw   (128x128 = [128,128]@[128,128]),  qbw = Ww2 @ Qb
// one block per output row o; 128 threads, one output col each
// ---------------------------------------------------------------------------
__global__ __launch_bounds__(128) void qc_kernel(const float* __restrict__ Qw,
                                                 const float* __restrict__ Qb,
                                                 const float* __restrict__ Ww) {
    __shared__ float wrow[F];
    int o = blockIdx.x;
    int t = threadIdx.x;
    wrow[t] = Ww[(size_t)o * KCAT + F + t];  // Ww2 row o
    __syncthreads();
    float s = 0.0f;
#pragma unroll 8
    for (int k = 0; k < F; k++) s += wrow[k] * Qw[(size_t)k * F + t];
    g_Qc[o * F + t] = s;
    if (t == 0) {
        float qb = 0.0f;
        for (int k = 0; k < F; k++) qb += wrow[k] * Qb[k];
        g_qbw[o] = qb;
    }
}

// ---------------------------------------------------------------------------
// Warp-per-node aggregation: aggmean[n] = (sum_e w_e * h[src_e]) / wsum
// ---------------------------------------------------------------------------
__global__ __launch_bounds__(256) void agg_kernel(const float* __restrict__ h) {
    int warp = (blockIdx.x * blockDim.x + threadIdx.x) >> 5;
    int lane = threadIdx.x & 31;
    if (warp >= N_NODES) return;

    int j0 = g_offsets[warp];
    int j1 = g_offsets[warp + 1];

    float4 acc = make_float4(0.f, 0.f, 0.f, 0.f);
    float wsum = 0.0f;

    for (int base = j0; base < j1; base += 32) {
        int m = j1 - base; if (m > 32) m = 32;
        int2 p = (lane < m) ? g_pairs[base + lane] : make_int2(0, 0);
        for (int t = 0; t < m; t++) {
            int s = __shfl_sync(0xffffffffu, p.x, t);
            float we = __int_as_float(__shfl_sync(0xffffffffu, p.y, t));
            float4 v = *reinterpret_cast<const float4*>(&h[(size_t)s * F + lane * 4]);
            acc.x += we * v.x;
            acc.y += we * v.y;
            acc.z += we * v.z;
            acc.w += we * v.w;
            wsum += we;
        }
    }

    float winv = (wsum == 0.0f) ? 1.0f : 1.0f / wsum;
    acc.x *= winv; acc.y *= winv; acc.z *= winv; acc.w *= winv;
    *reinterpret_cast<float4*>(&g_aggmean[(size_t)warp * F + lane * 4]) = acc;
    if (lane == 0) g_has[warp] = (wsum != 0.0f) ? 1.0f : 0.0f;
}

// ---------------------------------------------------------------------------
// Fused GEMM: out = l2norm(leaky(h@Ww1^T + aggmean@Qc^T + Wb + has*qbw))
// block: 256 threads, tile 64 rows x 128 cols, per-thread 8x4
// ---------------------------------------------------------------------------
__global__ __launch_bounds__(256) void gemm_kernel(
    const float* __restrict__ h, const float* __restrict__ Ww,
    const float* __restrict__ Wb, float* __restrict__ out)
{
    __shared__ float As[BM][33];
    __shared__ float Bs[F][33];

    const int tid = threadIdx.x;
    const int tx = tid & 31;   // col group (4 cols each)
    const int ty = tid >> 5;   // row group (8 rows each)
    const int row0 = blockIdx.x * BM;

    float acc[8][4];
#pragma unroll
    for (int i = 0; i < 8; i++)
#pragma unroll
        for (int j = 0; j < 4; j++) acc[i][j] = 0.0f;

    for (int kc = 0; kc < KCAT; kc += 32) {
        const bool second = (kc >= F);
#pragma unroll
        for (int it = 0; it < 8; it++) {
            int q = tid + it * 256;
            int r = q >> 5, k = q & 31;
            int gr = row0 + r;
            float v = 0.0f;
            if (gr < N_NODES) {
                if (!second) v = h[(size_t)gr * F + kc + k];
                else         v = g_aggmean[(size_t)gr * F + (kc - F) + k];
            }
            As[r][k] = v;
        }
#pragma unroll
        for (int it = 0; it < 16; it++) {
            int q = tid + it * 256;
            int n = q >> 5, k = q & 31;
            float v;
            if (!second) v = Ww[(size_t)n * KCAT + kc + k];
            else         v = g_Qc[n * F + (kc - F) + k];
            Bs[n][k] = v;
        }
        __syncthreads();

#pragma unroll
        for (int kk = 0; kk < 32; kk++) {
            float a[8], b[4];
#pragma unroll
            for (int i = 0; i < 8; i++) a[i] = As[ty * 8 + i][kk];
#pragma unroll
            for (int j = 0; j < 4; j++) b[j] = Bs[tx * 4 + j][kk];
#pragma unroll
            for (int i = 0; i < 8; i++)
#pragma unroll
                for (int j = 0; j < 4; j++) acc[i][j] += a[i] * b[j];
        }
        __syncthreads();
    }

    float wb[4], qb2[4];
#pragma unroll
    for (int j = 0; j < 4; j++) {
        wb[j]  = Wb[tx * 4 + j];
        qb2[j] = g_qbw[tx * 4 + j];
    }

    // leaky relu + row sum-of-squares (lanes of a warp cover the 128 cols)
    float vout[8][4];
    float sq[8];
#pragma unroll
    for (int i = 0; i < 8; i++) {
        int gr = row0 + ty * 8 + i;
        float hasv = (gr < N_NODES) ? g_has[gr] : 0.0f;
        sq[i] = 0.0f;
#pragma unroll
        for (int j = 0; j < 4; j++) {
            float v = acc[i][j] + wb[j] + hasv * qb2[j];
            v = (v > 0.0f) ? v : 0.01f * v;
            vout[i][j] = v;
            sq[i] += v * v;
        }
    }
#pragma unroll
    for (int i = 0; i < 8; i++) {
#pragma unroll
        for (int off = 16; off > 0; off >>= 1)
            sq[i] += __shfl_xor_sync(0xffffffffu, sq[i], off);
    }

#pragma unroll
    for (int i = 0; i < 8; i++) {
        int gr = row0 + ty * 8 + i;
        if (gr < N_NODES) {
            float nrm = sqrtf(sq[i]);
            float inv = (nrm == 0.0f) ? 1.0f : 1.0f / nrm;
            float4 o;
            o.x = vout[i][0] * inv;
            o.y = vout[i][1] * inv;
            o.z = vout[i][2] * inv;
            o.w = vout[i][3] * inv;
            *reinterpret_cast<float4*>(&out[(size_t)gr * F + tx * 4]) = o;
        }
    }
}

// ---------------------------------------------------------------------------
// Launch
// Inputs: 0:h 1:ppr_weight 2:Qw 3:Qb 4:Ww 5:Wb 6:src 7:dst
// ---------------------------------------------------------------------------
extern "C" void kernel_launch(void* const* d_in, const int* in_sizes, int n_in,
                              void* d_out, int out_size) {
    const float* h   = (const float*)d_in[0];
    const float* ppr = (const float*)d_in[1];
    const float* Qw  = (const float*)d_in[2];
    const float* Qb  = (const float*)d_in[3];
    const float* Ww  = (const float*)d_in[4];
    const float* Wb  = (const float*)d_in[5];
    const int*   src = (const int*)d_in[6];
    const int*   dst = (const int*)d_in[7];
    float* out = (float*)d_out;

    zero_kernel <<<(N_NODES + 255) / 256, 256>>>();
    hist_kernel <<<(N_EDGES + 255) / 256, 256>>>(dst);
    scanA_kernel<<<NB_SCAN, 1024>>>();
    scanB_kernel<<<1, 32>>>();
    scanC_kernel<<<NB_SCAN, 1024>>>();
    build_kernel<<<(N_EDGES + 255) / 256, 256>>>(src, dst, ppr);
    qc_kernel   <<<F, F>>>(Qw, Qb, Ww);
    agg_kernel  <<<(N_NODES + 7) / 8, 256>>>(h);
    gemm_kernel <<<(N_NODES + BM - 1) / BM, 256>>>(h, Ww, Wb, out);
}

// round 4
// speedup vs baseline: 2.3777x; 1.6714x over previous
#include <cuda_runtime.h>
#include <cuda_bf16.h>
#include <cstdint>
#include <cstddef>

#define N_NODES 50000
#define N_EDGES 800000
#define F 128
#define KCAT 256
#define NB_SCAN 49   // ceil(50000/1024)

// ---------------------------------------------------------------------------
// Scratch (static device globals — no allocation)
// ---------------------------------------------------------------------------
__device__ int   g_counts[N_NODES];
__device__ int   g_cursor[N_NODES];
__device__ int   g_offsets[N_NODES + 1];
__device__ int   g_bsum[NB_SCAN];
__device__ int   g_bsumex[NB_SCAN];
__device__ int2  g_pairs[N_EDGES];               // {src, bitcast(weight)} CSR by dst
__device__ float g_aggmean[(size_t)N_NODES * F]; // segsum(w*h[src]) / wsum
__device__ float g_has[N_NODES];                 // 1 if node has incoming edges
__device__ float g_Qc[F * F];                    // Ww2 @ Qw
__device__ float g_qbw[F];                       // Ww2 @ Qb
__device__ __nv_bfloat16 g_Bhi[F * KCAT];        // combined weight, bf16 hi
__device__ __nv_bfloat16 g_Blo[F * KCAT];        // combined weight, bf16 lo

// ---------------------------------------------------------------------------
// Zero histogram + cursor
// ---------------------------------------------------------------------------
__global__ void zero_kernel() {
    int i = blockIdx.x * blockDim.x + threadIdx.x;
    if (i < N_NODES) { g_counts[i] = 0; g_cursor[i] = 0; }
}

// ---------------------------------------------------------------------------
// Histogram of dst
// ---------------------------------------------------------------------------
__global__ void hist_kernel(const int* __restrict__ dst) {
    int e = blockIdx.x * blockDim.x + threadIdx.x;
    if (e < N_EDGES) atomicAdd(&g_counts[dst[e]], 1);
}

// ---------------------------------------------------------------------------
// Exclusive scan over g_counts -> g_offsets (3 stages)
// ---------------------------------------------------------------------------
__global__ __launch_bounds__(1024) void scanA_kernel() {
    __shared__ int sd[1024];
    int t = threadIdx.x;
    int i = blockIdx.x * 1024 + t;
    int v = (i < N_NODES) ? g_counts[i] : 0;
    sd[t] = v;
    __syncthreads();
    for (int off = 1; off < 1024; off <<= 1) {
        int add = (t >= off) ? sd[t - off] : 0;
        __syncthreads();
        sd[t] += add;
        __syncthreads();
    }
    int incl = sd[t];
    if (i < N_NODES) g_offsets[i] = incl - v;
    if (t == 1023) g_bsum[blockIdx.x] = incl;
}

__global__ void scanB_kernel() {   // 64-thread scan over 49 block sums
    __shared__ int ws[2];
    int t = threadIdx.x;
    int lane = t & 31, w = t >> 5;
    int v = (t < NB_SCAN) ? g_bsum[t] : 0;
    int x = v;
#pragma unroll
    for (int o = 1; o < 32; o <<= 1) {
        int y = __shfl_up_sync(0xffffffffu, x, o);
        if (lane >= o) x += y;
    }
    if (lane == 31) ws[w] = x;
    __syncthreads();
    if (w == 1) x += ws[0];
    if (t < NB_SCAN) g_bsumex[t] = x - v;
}

__global__ __launch_bounds__(1024) void scanC_kernel() {
    int t = threadIdx.x;
    int i = blockIdx.x * 1024 + t;
    if (i < N_NODES) g_offsets[i] += g_bsumex[blockIdx.x];
    if (blockIdx.x == 0 && t == 0) g_offsets[N_NODES] = N_EDGES;
}

// ---------------------------------------------------------------------------
// Bucket-build: sort (src, w) pairs by dst into CSR order
// ---------------------------------------------------------------------------
__global__ void build_kernel(const int* __restrict__ src, const int* __restrict__ dst,
                             const float* __restrict__ w) {
    int e = blockIdx.x * blockDim.x + threadIdx.x;
    if (e < N_EDGES) {
        int d = dst[e];
        int pos = g_offsets[d] + atomicAdd(&g_cursor[d], 1);
        g_pairs[pos] = make_int2(src[e], __float_as_int(w[e]));
    }
}

// ---------------------------------------------------------------------------
// Qc = Ww2 @ Qw, qbw = Ww2 @ Qb
// ---------------------------------------------------------------------------
__global__ __launch_bounds__(128) void qc_kernel(const float* __restrict__ Qw,
                                                 const float* __restrict__ Qb,
                                                 const float* __restrict__ Ww) {
    __shared__ float wrow[F];
    int o = blockIdx.x;
    int t = threadIdx.x;
    wrow[t] = Ww[(size_t)o * KCAT + F + t];
    __syncthreads();
    float s = 0.0f;
#pragma unroll 8
    for (int k = 0; k < F; k++) s += wrow[k] * Qw[(size_t)k * F + t];
    g_Qc[o * F + t] = s;
    if (t == 0) {
        float qb = 0.0f;
        for (int k = 0; k < F; k++) qb += wrow[k] * Qb[k];
        g_qbw[o] = qb;
    }
}

// ---------------------------------------------------------------------------
// Combined weight matrix -> bf16 hi/lo:  W[n][k] = k<F ? Ww[n][k] : Qc[n][k-F]
// ---------------------------------------------------------------------------
__global__ void bprep_kernel(const float* __restrict__ Ww) {
    int i = blockIdx.x * blockDim.x + threadIdx.x;
    if (i < F * KCAT) {
        int n = i / KCAT, k = i % KCAT;
        float wv = (k < F) ? Ww[(size_t)n * KCAT + k] : g_Qc[n * F + (k - F)];
        __nv_bfloat16 hi = __float2bfloat16(wv);
        float lo = wv - __bfloat162float(hi);
        g_Bhi[i] = hi;
        g_Blo[i] = __float2bfloat16(lo);
    }
}

// ---------------------------------------------------------------------------
// Warp-per-node aggregation: aggmean[n] = (sum_e w_e * h[src_e]) / wsum
// ---------------------------------------------------------------------------
__global__ __launch_bounds__(256) void agg_kernel(const float* __restrict__ h) {
    int warp = (blockIdx.x * blockDim.x + threadIdx.x) >> 5;
    int lane = threadIdx.x & 31;
    if (warp >= N_NODES) return;

    int j0 = g_offsets[warp];
    int j1 = g_offsets[warp + 1];

    float4 acc = make_float4(0.f, 0.f, 0.f, 0.f);
    float wsum = 0.0f;

    for (int base = j0; base < j1; base += 32) {
        int m = j1 - base; if (m > 32) m = 32;
        int2 p = (lane < m) ? g_pairs[base + lane] : make_int2(0, 0);
        for (int t = 0; t < m; t++) {
            int s = __shfl_sync(0xffffffffu, p.x, t);
            float we = __int_as_float(__shfl_sync(0xffffffffu, p.y, t));
            float4 v = *reinterpret_cast<const float4*>(&h[(size_t)s * F + lane * 4]);
            acc.x += we * v.x;
            acc.y += we * v.y;
            acc.z += we * v.z;
            acc.w += we * v.w;
            wsum += we;
        }
    }

    float winv = (wsum == 0.0f) ? 1.0f : 1.0f / wsum;
    acc.x *= winv; acc.y *= winv; acc.z *= winv; acc.w *= winv;
    *reinterpret_cast<float4*>(&g_aggmean[(size_t)warp * F + lane * 4]) = acc;
    if (lane == 0) g_has[warp] = (wsum != 0.0f) ? 1.0f : 0.0f;
}

// ---------------------------------------------------------------------------
// HMMA (mma.sync bf16x3) GEMM + epilogue:
//   out = l2norm(leaky(concat[h, aggmean] @ W^T + Wb + has*qbw))
// CTA tile: M=128, N=128, K=256 in 4 chunks of 64.
// SMEM: Ahi/Alo/Bhi/Blo as [128][64] bf16 with 72-half row stride.
// Warp tiling: 2 warps in M (64 rows), 4 in N (32 cols); 16 mma per k-step.
// ---------------------------------------------------------------------------
#define ASTRIDE 72                      // halves per row (64 + 8 pad)
#define TILE_HALVES (128 * ASTRIDE)     // 9216 halves = 18432 B
#define SM_AHI 0
#define SM_ALO (SM_AHI + TILE_HALVES * 2)
#define SM_BHI (SM_ALO + TILE_HALVES * 2)
#define SM_BLO (SM_BHI + TILE_HALVES * 2)
#define SM_TILES_END (SM_BLO + TILE_HALVES * 2)   // 73728
#define STG_STRIDE 132                  // floats per staged row
#define SM_WB  SM_TILES_END             // 512 B
#define SM_QBW (SM_WB + 512)            // 512 B
#define SM_TOTAL (SM_QBW + 512)         // 74752 B (stage reuses tile region)

__device__ __forceinline__ void mma_bf16(float& d0, float& d1, float& d2, float& d3,
                                         uint32_t a0, uint32_t a1, uint32_t a2, uint32_t a3,
                                         uint32_t b0, uint32_t b1) {
    asm volatile(
        "mma.sync.aligned.m16n8k16.row.col.f32.bf16.bf16.f32 "
        "{%0,%1,%2,%3}, {%4,%5,%6,%7}, {%8,%9}, {%0,%1,%2,%3};"
        : "+f"(d0), "+f"(d1), "+f"(d2), "+f"(d3)
        : "r"(a0), "r"(a1), "r"(a2), "r"(a3), "r"(b0), "r"(b1));
}

__global__ __launch_bounds__(256) void mmagemm_kernel(
    const float* __restrict__ h, const float* __restrict__ Wb,
    float* __restrict__ out)
{
    extern __shared__ char smem[];
    __nv_bfloat16* sAhi = (__nv_bfloat16*)(smem + SM_AHI);
    __nv_bfloat16* sAlo = (__nv_bfloat16*)(smem + SM_ALO);
    __nv_bfloat16* sBhi = (__nv_bfloat16*)(smem + SM_BHI);
    __nv_bfloat16* sBlo = (__nv_bfloat16*)(smem + SM_BLO);
    float* sStage = (float*)(smem + SM_AHI);          // reused after mainloop
    float* sWb    = (float*)(smem + SM_WB);
    float* sQbw   = (float*)(smem + SM_QBW);

    const int tid  = threadIdx.x;
    const int wid  = tid >> 5;
    const int lane = tid & 31;
    const int row0 = blockIdx.x * 128;

    if (tid < 128) {
        sWb[tid]  = Wb[tid];
        sQbw[tid] = g_qbw[tid];
    }

    // warp tile origin
    const int m0 = (wid & 1) * 64;
    const int n0 = (wid >> 1) * 32;
    const int qrow = lane >> 2;           // 0..7
    const int qcol = (lane & 3) * 2;      // 0,2,4,6

    float acc[4][4][4];
#pragma unroll
    for (int mt = 0; mt < 4; mt++)
#pragma unroll
        for (int nt = 0; nt < 4; nt++)
#pragma unroll
            for (int r = 0; r < 4; r++) acc[mt][nt][r] = 0.0f;

    // loader mapping: thread -> (row, 32-col half)
    const int ar  = tid >> 1;            // 0..127
    const int acb = (tid & 1) * 32;      // 0 or 32
    const int grow_a = row0 + ar;
    const bool valid_a = (grow_a < N_NODES);

    for (int c = 0; c < 4; c++) {
        __syncthreads();
        // ---- A tile: fp32 -> bf16 hi/lo split ----
        {
            const float* srcp = (c < 2) ? h : g_aggmean;
            const int colofs = (c & 1) * 64;
            const float* rowp = srcp + (size_t)grow_a * F + colofs + acb;
            __nv_bfloat16* dhi = &sAhi[ar * ASTRIDE + acb];
            __nv_bfloat16* dlo = &sAlo[ar * ASTRIDE + acb];
#pragma unroll
            for (int j = 0; j < 8; j++) {
                float4 x = valid_a ? *reinterpret_cast<const float4*>(rowp + j * 4)
                                   : make_float4(0.f, 0.f, 0.f, 0.f);
                __nv_bfloat16 h0 = __float2bfloat16(x.x);
                __nv_bfloat16 h1 = __float2bfloat16(x.y);
                __nv_bfloat16 h2 = __float2bfloat16(x.z);
                __nv_bfloat16 h3 = __float2bfloat16(x.w);
                __nv_bfloat162 hp0(h0, h1), hp1(h2, h3);
                __nv_bfloat162 lp0 = __floats2bfloat162_rn(x.x - __bfloat162float(h0),
                                                           x.y - __bfloat162float(h1));
                __nv_bfloat162 lp1 = __floats2bfloat162_rn(x.z - __bfloat162float(h2),
                                                           x.w - __bfloat162float(h3));
                *reinterpret_cast<uint2*>(dhi + j * 4) =
                    make_uint2(*(uint32_t*)&hp0, *(uint32_t*)&hp1);
                *reinterpret_cast<uint2*>(dlo + j * 4) =
                    make_uint2(*(uint32_t*)&lp0, *(uint32_t*)&lp1);
            }
        }
        // ---- B tile: copy precomputed bf16 hi/lo ----
        {
            const int n  = tid >> 1;
            const int kb = (tid & 1) * 32;
            const size_t gofs = (size_t)n * KCAT + c * 64 + kb;
            const int sofs = n * ASTRIDE + kb;
#pragma unroll
            for (int j = 0; j < 4; j++) {
                *reinterpret_cast<uint4*>(&sBhi[sofs + j * 8]) =
                    *reinterpret_cast<const uint4*>(&g_Bhi[gofs + j * 8]);
                *reinterpret_cast<uint4*>(&sBlo[sofs + j * 8]) =
                    *reinterpret_cast<const uint4*>(&g_Blo[gofs + j * 8]);
            }
        }
        __syncthreads();

        // ---- compute: 3 splits x 4 k-steps x 16 mma ----
#pragma unroll
        for (int s = 0; s < 3; s++) {
            const __nv_bfloat16* pA = (s == 2) ? sAlo : sAhi;
            const __nv_bfloat16* pB = (s == 1) ? sBlo : sBhi;
#pragma unroll
            for (int ks = 0; ks < 4; ks++) {
                const int k0 = ks * 16;
                uint32_t bf[4][2];
#pragma unroll
                for (int nt = 0; nt < 4; nt++) {
                    const __nv_bfloat16* bp =
                        pB + (n0 + nt * 8 + qrow) * ASTRIDE + k0 + qcol;
                    bf[nt][0] = *reinterpret_cast<const uint32_t*>(bp);
                    bf[nt][1] = *reinterpret_cast<const uint32_t*>(bp + 8);
                }
                uint32_t af[4][4];
#pragma unroll
                for (int mt = 0; mt < 4; mt++) {
                    const __nv_bfloat16* ap =
                        pA + (m0 + mt * 16 + qrow) * ASTRIDE + k0 + qcol;
                    af[mt][0] = *reinterpret_cast<const uint32_t*>(ap);
                    af[mt][1] = *reinterpret_cast<const uint32_t*>(ap + 8 * ASTRIDE);
                    af[mt][2] = *reinterpret_cast<const uint32_t*>(ap + 8);
                    af[mt][3] = *reinterpret_cast<const uint32_t*>(ap + 8 * ASTRIDE + 8);
                }
#pragma unroll
                for (int mt = 0; mt < 4; mt++)
#pragma unroll
                    for (int nt = 0; nt < 4; nt++)
                        mma_bf16(acc[mt][nt][0], acc[mt][nt][1],
                                 acc[mt][nt][2], acc[mt][nt][3],
                                 af[mt][0], af[mt][1], af[mt][2], af[mt][3],
                                 bf[nt][0], bf[nt][1]);
            }
        }
    }

    // ---- stage accumulators to smem (reuse tile region) ----
    __syncthreads();
#pragma unroll
    for (int mt = 0; mt < 4; mt++) {
        const int r = m0 + mt * 16 + qrow;
#pragma unroll
        for (int nt = 0; nt < 4; nt++) {
            const int ccol = n0 + nt * 8 + qcol;
            *reinterpret_cast<float2*>(&sStage[r * STG_STRIDE + ccol]) =
                make_float2(acc[mt][nt][0], acc[mt][nt][1]);
            *reinterpret_cast<float2*>(&sStage[(r + 8) * STG_STRIDE + ccol]) =
                make_float2(acc[mt][nt][2], acc[mt][nt][3]);
        }
    }
    __syncthreads();

    // ---- epilogue: bias + leaky + L2 norm; thread owns half a row ----
    {
        const int r = tid >> 1;
        const int cb = (tid & 1) * 64;
        const int grow = row0 + r;
        const bool valid = (grow < N_NODES);
        const float hasv = valid ? g_has[grow] : 0.0f;

        float vals[64];
        float sq = 0.0f;
#pragma unroll
        for (int j = 0; j < 16; j++) {
            float4 x = *reinterpret_cast<const float4*>(&sStage[r * STG_STRIDE + cb + j * 4]);
            float v0 = x.x + sWb[cb + j*4 + 0] + hasv * sQbw[cb + j*4 + 0];
            float v1 = x.y + sWb[cb + j*4 + 1] + hasv * sQbw[cb + j*4 + 1];
            float v2 = x.z + sWb[cb + j*4 + 2] + hasv * sQbw[cb + j*4 + 2];
            float v3 = x.w + sWb[cb + j*4 + 3] + hasv * sQbw[cb + j*4 + 3];
            v0 = (v0 > 0.0f) ? v0 : 0.01f * v0;
            v1 = (v1 > 0.0f) ? v1 : 0.01f * v1;
            v2 = (v2 > 0.0f) ? v2 : 0.01f * v2;
            v3 = (v3 > 0.0f) ? v3 : 0.01f * v3;
            vals[j*4+0] = v0; vals[j*4+1] = v1; vals[j*4+2] = v2; vals[j*4+3] = v3;
            sq += v0 * v0 + v1 * v1 + v2 * v2 + v3 * v3;
        }
        sq += __shfl_xor_sync(0xffffffffu, sq, 1);
        float nrm = sqrtf(sq);
        float inv = (nrm == 0.0f) ? 1.0f : 1.0f / nrm;

        if (valid) {
#pragma unroll
            for (int j = 0; j < 16; j++) {
                float4 o;
                o.x = vals[j*4+0] * inv;
                o.y = vals[j*4+1] * inv;
                o.z = vals[j*4+2] * inv;
                o.w = vals[j*4+3] * inv;
                *reinterpret_cast<float4*>(&out[(size_t)grow * F + cb + j * 4]) = o;
            }
        }
    }
}

// ---------------------------------------------------------------------------
// Launch
// Inputs: 0:h 1:ppr_weight 2:Qw 3:Qb 4:Ww 5:Wb 6:src 7:dst
// ---------------------------------------------------------------------------
extern "C" void kernel_launch(void* const* d_in, const int* in_sizes, int n_in,
                              void* d_out, int out_size) {
    const float* h   = (const float*)d_in[0];
    const float* ppr = (const float*)d_in[1];
    const float* Qw  = (const float*)d_in[2];
    const float* Qb  = (const float*)d_in[3];
    const float* Ww  = (const float*)d_in[4];
    const float* Wb  = (const float*)d_in[5];
    const int*   src = (const int*)d_in[6];
    const int*   dst = (const int*)d_in[7];
    float* out = (float*)d_out;

    cudaFuncSetAttribute(mmagemm_kernel,
                         cudaFuncAttributeMaxDynamicSharedMemorySize, SM_TOTAL);

    zero_kernel <<<(N_NODES + 255) / 256, 256>>>();
    hist_kernel <<<(N_EDGES + 255) / 256, 256>>>(dst);
    scanA_kernel<<<NB_SCAN, 1024>>>();
    scanB_kernel<<<1, 64>>>();
    scanC_kernel<<<NB_SCAN, 1024>>>();
    build_kernel<<<(N_EDGES + 255) / 256, 256>>>(src, dst, ppr);
    qc_kernel   <<<F, F>>>(Qw, Qb, Ww);
    bprep_kernel<<<(F * KCAT + 255) / 256, 256>>>(Ww);
    agg_kernel  <<<(N_NODES + 7) / 8, 256>>>(h);
    mmagemm_kernel<<<(N_NODES + 127) / 128, 256, SM_TOTAL>>>(h, Wb, out);
}

// round 6
// speedup vs baseline: 2.4230x; 1.0190x over previous
#include <cuda_runtime.h>
#include <cuda_bf16.h>
#include <cstdint>
#include <cstddef>

#define N_NODES 50000
#define N_EDGES 800000
#define F 128
#define KCAT 256
#define NB_SCAN 49   // ceil(50000/1024)

// ---------------------------------------------------------------------------
// Scratch (static device globals — no allocation)
// ---------------------------------------------------------------------------
__device__ int   g_counts[N_NODES];
__device__ int   g_cursor[N_NODES];
__device__ int   g_offsets[N_NODES + 1];
__device__ int   g_bsum[NB_SCAN];
__device__ int2  g_pairs[N_EDGES];               // {src, bitcast(weight)} CSR by dst
__device__ float g_aggmean[(size_t)N_NODES * F]; // segsum(w*h[src]) / wsum
__device__ float g_has[N_NODES];                 // 1 if node has incoming edges
__device__ float g_qbw[F];                       // Ww2 @ Qb
__device__ __nv_bfloat16 g_Bhi[F * KCAT];        // combined weight, bf16 hi
__device__ __nv_bfloat16 g_Blo[F * KCAT];        // combined weight, bf16 lo

// ---------------------------------------------------------------------------
// Histogram of dst
// ---------------------------------------------------------------------------
__global__ void hist_kernel(const int* __restrict__ dst) {
    int e = blockIdx.x * blockDim.x + threadIdx.x;
    if (e < N_EDGES) atomicAdd(&g_counts[dst[e]], 1);
}

// ---------------------------------------------------------------------------
// Scan stage A: block-local exclusive scan + per-block sums
// ---------------------------------------------------------------------------
__global__ __launch_bounds__(1024) void scanA_kernel() {
    __shared__ int sd[1024];
    int t = threadIdx.x;
    int i = blockIdx.x * 1024 + t;
    int v = (i < N_NODES) ? g_counts[i] : 0;
    sd[t] = v;
    __syncthreads();
    for (int off = 1; off < 1024; off <<= 1) {
        int add = (t >= off) ? sd[t - off] : 0;
        __syncthreads();
        sd[t] += add;
        __syncthreads();
    }
    int incl = sd[t];
    if (i < N_NODES) g_offsets[i] = incl - v;
    if (t == 1023) g_bsum[blockIdx.x] = incl;
}

// ---------------------------------------------------------------------------
// Scan stage C (fused B+C): warp 0 of every block redundantly scans the 49
// block sums (two 32-wide shfl chunks, no cross-warp traffic), stores the
// exclusive prefixes, then all threads apply this block's prefix and also
// seed g_cursor with the final offsets.
// ---------------------------------------------------------------------------
__global__ __launch_bounds__(1024) void scanC_kernel() {
    __shared__ int spref[64];
    int t = threadIdx.x;
    if (t < 32) {
        // chunk 0: elements 0..31
        int v0 = g_bsum[t];
        int x0 = v0;
#pragma unroll
        for (int o = 1; o < 32; o <<= 1) {
            int y = __shfl_up_sync(0xffffffffu, x0, o);
            if (t >= o) x0 += y;
        }
        int tot0 = __shfl_sync(0xffffffffu, x0, 31);
        // chunk 1: elements 32..48
        int i1 = 32 + t;
        int v1 = (i1 < NB_SCAN) ? g_bsum[i1] : 0;
        int x1 = v1;
#pragma unroll
        for (int o = 1; o < 32; o <<= 1) {
            int y = __shfl_up_sync(0xffffffffu, x1, o);
            if (t >= o) x1 += y;
        }
        spref[t] = x0 - v0;
        spref[i1] = x1 + tot0 - v1;
    }
    __syncthreads();   // single convergent barrier for all 1024 threads

    int sbase = spref[blockIdx.x];
    int i = blockIdx.x * 1024 + t;
    if (i < N_NODES) {
        int o = g_offsets[i] + sbase;
        g_offsets[i] = o;
        g_cursor[i]  = o;
    }
    if (blockIdx.x == 0 && t == 0) g_offsets[N_NODES] = N_EDGES;
}

// ---------------------------------------------------------------------------
// Bucket-build: sort (src, w) pairs by dst into CSR order
// (g_cursor pre-seeded with offsets by scanC)
// ---------------------------------------------------------------------------
__global__ void build_kernel(const int* __restrict__ src, const int* __restrict__ dst,
                             const float* __restrict__ w) {
    int e = blockIdx.x * blockDim.x + threadIdx.x;
    if (e < N_EDGES) {
        int pos = atomicAdd(&g_cursor[dst[e]], 1);
        g_pairs[pos] = make_int2(src[e], __float_as_int(w[e]));
    }
}

// ---------------------------------------------------------------------------
// Fused Qc + weight prep:
//   Qc[o][t] = sum_k Ww2[o][k] Qw[k][t];  qbw[o] = sum_k Ww2[o][k] Qb[k]
//   Bhi/Blo[o][k] = split( k<F ? Ww[o][k] : Qc[o][k-F] )
// ---------------------------------------------------------------------------
__global__ __launch_bounds__(128) void qcprep_kernel(const float* __restrict__ Qw,
                                                     const float* __restrict__ Qb,
                                                     const float* __restrict__ Ww) {
    __shared__ float wrow[F];
    __shared__ float part[F];
    int o = blockIdx.x;
    int t = threadIdx.x;
    float w2 = Ww[(size_t)o * KCAT + F + t];
    wrow[t] = w2;
    part[t] = w2 * Qb[t];
    __syncthreads();
    float s = 0.0f;
#pragma unroll 8
    for (int k = 0; k < F; k++) s += wrow[k] * Qw[(size_t)k * F + t];

    // first half: Ww1
    float w1 = Ww[(size_t)o * KCAT + t];
    __nv_bfloat16 hi1 = __float2bfloat16(w1);
    g_Bhi[o * KCAT + t] = hi1;
    g_Blo[o * KCAT + t] = __float2bfloat16(w1 - __bfloat162float(hi1));
    // second half: Qc
    __nv_bfloat16 hi2 = __float2bfloat16(s);
    g_Bhi[o * KCAT + F + t] = hi2;
    g_Blo[o * KCAT + F + t] = __float2bfloat16(s - __bfloat162float(hi2));

    if (t == 0) {
        float qb = 0.0f;
        for (int k = 0; k < F; k++) qb += part[k];
        g_qbw[o] = qb;
    }
}

// ---------------------------------------------------------------------------
// Warp-per-node aggregation: aggmean[n] = (sum_e w_e * h[src_e]) / wsum
// ---------------------------------------------------------------------------
__global__ __launch_bounds__(256) void agg_kernel(const float* __restrict__ h) {
    int warp = (blockIdx.x * blockDim.x + threadIdx.x) >> 5;
    int lane = threadIdx.x & 31;
    if (warp >= N_NODES) return;

    int j0 = g_offsets[warp];
    int j1 = g_offsets[warp + 1];

    float4 acc = make_float4(0.f, 0.f, 0.f, 0.f);
    float wsum = 0.0f;

    for (int base = j0; base < j1; base += 32) {
        int m = j1 - base; if (m > 32) m = 32;
        int2 p = (lane < m) ? g_pairs[base + lane] : make_int2(0, 0);
#pragma unroll 4
        for (int t = 0; t < m; t++) {
            int s = __shfl_sync(0xffffffffu, p.x, t);
            float we = __int_as_float(__shfl_sync(0xffffffffu, p.y, t));
            float4 v = *reinterpret_cast<const float4*>(&h[(size_t)s * F + lane * 4]);
            acc.x += we * v.x;
            acc.y += we * v.y;
            acc.z += we * v.z;
            acc.w += we * v.w;
            wsum += we;
        }
    }

    float winv = (wsum == 0.0f) ? 1.0f : 1.0f / wsum;
    acc.x *= winv; acc.y *= winv; acc.z *= winv; acc.w *= winv;
    *reinterpret_cast<float4*>(&g_aggmean[(size_t)warp * F + lane * 4]) = acc;
    if (lane == 0) g_has[warp] = (wsum != 0.0f) ? 1.0f : 0.0f;
}

// ---------------------------------------------------------------------------
// HMMA (mma.sync bf16x3) GEMM + epilogue:
//   out = l2norm(leaky(concat[h, aggmean] @ W^T + Wb + has*qbw))
// CTA tile: M=128, N=128, K=256 in 4 chunks of 64.
// ---------------------------------------------------------------------------
#define ASTRIDE 72                      // halves per row (64 + 8 pad)
#define TILE_HALVES (128 * ASTRIDE)     // 9216 halves = 18432 B
#define SM_AHI 0
#define SM_ALO (SM_AHI + TILE_HALVES * 2)
#define SM_BHI (SM_ALO + TILE_HALVES * 2)
#define SM_BLO (SM_BHI + TILE_HALVES * 2)
#define SM_TILES_END (SM_BLO + TILE_HALVES * 2)   // 73728
#define STG_STRIDE 132                  // floats per staged row
#define SM_WB  SM_TILES_END             // 512 B
#define SM_QBW (SM_WB + 512)            // 512 B
#define SM_TOTAL (SM_QBW + 512)         // 74752 B (stage reuses tile region)

__device__ __forceinline__ void mma_bf16(float& d0, float& d1, float& d2, float& d3,
                                         uint32_t a0, uint32_t a1, uint32_t a2, uint32_t a3,
                                         uint32_t b0, uint32_t b1) {
    asm volatile(
        "mma.sync.aligned.m16n8k16.row.col.f32.bf16.bf16.f32 "
        "{%0,%1,%2,%3}, {%4,%5,%6,%7}, {%8,%9}, {%0,%1,%2,%3};"
        : "+f"(d0), "+f"(d1), "+f"(d2), "+f"(d3)
        : "r"(a0), "r"(a1), "r"(a2), "r"(a3), "r"(b0), "r"(b1));
}

__global__ __launch_bounds__(256) void mmagemm_kernel(
    const float* __restrict__ h, const float* __restrict__ Wb,
    float* __restrict__ out)
{
    extern __shared__ char smem[];
    __nv_bfloat16* sAhi = (__nv_bfloat16*)(smem + SM_AHI);
    __nv_bfloat16* sAlo = (__nv_bfloat16*)(smem + SM_ALO);
    __nv_bfloat16* sBhi = (__nv_bfloat16*)(smem + SM_BHI);
    __nv_bfloat16* sBlo = (__nv_bfloat16*)(smem + SM_BLO);
    float* sStage = (float*)(smem + SM_AHI);          // reused after mainloop
    float* sWb    = (float*)(smem + SM_WB);
    float* sQbw   = (float*)(smem + SM_QBW);

    const int tid  = threadIdx.x;
    const int wid  = tid >> 5;
    const int lane = tid & 31;
    const int row0 = blockIdx.x * 128;

    if (tid < 128) {
        sWb[tid]  = Wb[tid];
        sQbw[tid] = g_qbw[tid];
    }

    // warp tile origin
    const int m0 = (wid & 1) * 64;
    const int n0 = (wid >> 1) * 32;
    const int qrow = lane >> 2;           // 0..7
    const int qcol = (lane & 3) * 2;      // 0,2,4,6

    float acc[4][4][4];
#pragma unroll
    for (int mt = 0; mt < 4; mt++)
#pragma unroll
        for (int nt = 0; nt < 4; nt++)
#pragma unroll
            for (int r = 0; r < 4; r++) acc[mt][nt][r] = 0.0f;

    // loader mapping: thread -> (row, 32-col half)
    const int ar  = tid >> 1;            // 0..127
    const int acb = (tid & 1) * 32;      // 0 or 32
    const int grow_a = row0 + ar;
    const bool valid_a = (grow_a < N_NODES);

    for (int c = 0; c < 4; c++) {
        __syncthreads();
        // ---- A tile: fp32 -> bf16 hi/lo split ----
        {
            const float* srcp = (c < 2) ? h : g_aggmean;
            const int colofs = (c & 1) * 64;
            const float* rowp = srcp + (size_t)grow_a * F + colofs + acb;
            __nv_bfloat16* dhi = &sAhi[ar * ASTRIDE + acb];
            __nv_bfloat16* dlo = &sAlo[ar * ASTRIDE + acb];
#pragma unroll
            for (int j = 0; j < 8; j++) {
                float4 x = valid_a ? *reinterpret_cast<const float4*>(rowp + j * 4)
                                   : make_float4(0.f, 0.f, 0.f, 0.f);
                __nv_bfloat16 h0 = __float2bfloat16(x.x);
                __nv_bfloat16 h1 = __float2bfloat16(x.y);
                __nv_bfloat16 h2 = __float2bfloat16(x.z);
                __nv_bfloat16 h3 = __float2bfloat16(x.w);
                __nv_bfloat162 hp0(h0, h1), hp1(h2, h3);
                __nv_bfloat162 lp0 = __floats2bfloat162_rn(x.x - __bfloat162float(h0),
                                                           x.y - __bfloat162float(h1));
                __nv_bfloat162 lp1 = __floats2bfloat162_rn(x.z - __bfloat162float(h2),
                                                           x.w - __bfloat162float(h3));
                *reinterpret_cast<uint2*>(dhi + j * 4) =
                    make_uint2(*(uint32_t*)&hp0, *(uint32_t*)&hp1);
                *reinterpret_cast<uint2*>(dlo + j * 4) =
                    make_uint2(*(uint32_t*)&lp0, *(uint32_t*)&lp1);
            }
        }
        // ---- B tile: copy precomputed bf16 hi/lo ----
        {
            const int n  = tid >> 1;
            const int kb = (tid & 1) * 32;
            const size_t gofs = (size_t)n * KCAT + c * 64 + kb;
            const int sofs = n * ASTRIDE + kb;
#pragma unroll
            for (int j = 0; j < 4; j++) {
                *reinterpret_cast<uint4*>(&sBhi[sofs + j * 8]) =
                    *reinterpret_cast<const uint4*>(&g_Bhi[gofs + j * 8]);
                *reinterpret_cast<uint4*>(&sBlo[sofs + j * 8]) =
                    *reinterpret_cast<const uint4*>(&g_Blo[gofs + j * 8]);
            }
        }
        __syncthreads();

        // ---- compute: 3 splits x 4 k-steps x 16 mma ----
#pragma unroll
        for (int s = 0; s < 3; s++) {
            const __nv_bfloat16* pA = (s == 2) ? sAlo : sAhi;
            const __nv_bfloat16* pB = (s == 1) ? sBlo : sBhi;
#pragma unroll
            for (int ks = 0; ks < 4; ks++) {
                const int k0 = ks * 16;
                uint32_t bf[4][2];
#pragma unroll
                for (int nt = 0; nt < 4; nt++) {
                    const __nv_bfloat16* bp =
                        pB + (n0 + nt * 8 + qrow) * ASTRIDE + k0 + qcol;
                    bf[nt][0] = *reinterpret_cast<const uint32_t*>(bp);
                    bf[nt][1] = *reinterpret_cast<const uint32_t*>(bp + 8);
                }
                uint32_t af[4][4];
#pragma unroll
                for (int mt = 0; mt < 4; mt++) {
                    const __nv_bfloat16* ap =
                        pA + (m0 + mt * 16 + qrow) * ASTRIDE + k0 + qcol;
                    af[mt][0] = *reinterpret_cast<const uint32_t*>(ap);
                    af[mt][1] = *reinterpret_cast<const uint32_t*>(ap + 8 * ASTRIDE);
                    af[mt][2] = *reinterpret_cast<const uint32_t*>(ap + 8);
                    af[mt][3] = *reinterpret_cast<const uint32_t*>(ap + 8 * ASTRIDE + 8);
                }
#pragma unroll
                for (int mt = 0; mt < 4; mt++)
#pragma unroll
                    for (int nt = 0; nt < 4; nt++)
                        mma_bf16(acc[mt][nt][0], acc[mt][nt][1],
                                 acc[mt][nt][2], acc[mt][nt][3],
                                 af[mt][0], af[mt][1], af[mt][2], af[mt][3],
                                 bf[nt][0], bf[nt][1]);
            }
        }
    }

    // ---- stage accumulators to smem (reuse tile region) ----
    __syncthreads();
#pragma unroll
    for (int mt = 0; mt < 4; mt++) {
        const int r = m0 + mt * 16 + qrow;
#pragma unroll
        for (int nt = 0; nt < 4; nt++) {
            const int ccol = n0 + nt * 8 + qcol;
            *reinterpret_cast<float2*>(&sStage[r * STG_STRIDE + ccol]) =
                make_float2(acc[mt][nt][0], acc[mt][nt][1]);
            *reinterpret_cast<float2*>(&sStage[(r + 8) * STG_STRIDE + ccol]) =
                make_float2(acc[mt][nt][2], acc[mt][nt][3]);
        }
    }
    __syncthreads();

    // ---- epilogue: bias + leaky + L2 norm; thread owns half a row ----
    {
        const int r = tid >> 1;
        const int cb = (tid & 1) * 64;
        const int grow = row0 + r;
        const bool valid = (grow < N_NODES);
        const float hasv = valid ? g_has[grow] : 0.0f;

        float vals[64];
        float sq = 0.0f;
#pragma unroll
        for (int j = 0; j < 16; j++) {
            float4 x = *reinterpret_cast<const float4*>(&sStage[r * STG_STRIDE + cb + j * 4]);
            float v0 = x.x + sWb[cb + j*4 + 0] + hasv * sQbw[cb + j*4 + 0];
            float v1 = x.y + sWb[cb + j*4 + 1] + hasv * sQbw[cb + j*4 + 1];
            float v2 = x.z + sWb[cb + j*4 + 2] + hasv * sQbw[cb + j*4 + 2];
            float v3 = x.w + sWb[cb + j*4 + 3] + hasv * sQbw[cb + j*4 + 3];
            v0 = (v0 > 0.0f) ? v0 : 0.01f * v0;
            v1 = (v1 > 0.0f) ? v1 : 0.01f * v1;
            v2 = (v2 > 0.0f) ? v2 : 0.01f * v2;
            v3 = (v3 > 0.0f) ? v3 : 0.01f * v3;
            vals[j*4+0] = v0; vals[j*4+1] = v1; vals[j*4+2] = v2; vals[j*4+3] = v3;
            sq += v0 * v0 + v1 * v1 + v2 * v2 + v3 * v3;
        }
        sq += __shfl_xor_sync(0xffffffffu, sq, 1);
        float nrm = sqrtf(sq);
        float inv = (nrm == 0.0f) ? 1.0f : 1.0f / nrm;

        if (valid) {
#pragma unroll
            for (int j = 0; j < 16; j++) {
                float4 o;
                o.x = vals[j*4+0] * inv;
                o.y = vals[j*4+1] * inv;
                o.z = vals[j*4+2] * inv;
                o.w = vals[j*4+3] * inv;
                *reinterpret_cast<float4*>(&out[(size_t)grow * F + cb + j * 4]) = o;
            }
        }
    }
}

// ---------------------------------------------------------------------------
// Launch
// Inputs: 0:h 1:ppr_weight 2:Qw 3:Qb 4:Ww 5:Wb 6:src 7:dst
// ---------------------------------------------------------------------------
extern "C" void kernel_launch(void* const* d_in, const int* in_sizes, int n_in,
                              void* d_out, int out_size) {
    const float* h   = (const float*)d_in[0];
    const float* ppr = (const float*)d_in[1];
    const float* Qw  = (const float*)d_in[2];
    const float* Qb  = (const float*)d_in[3];
    const float* Ww  = (const float*)d_in[4];
    const float* Wb  = (const float*)d_in[5];
    const int*   src = (const int*)d_in[6];
    const int*   dst = (const int*)d_in[7];
    float* out = (float*)d_out;

    cudaFuncSetAttribute(mmagemm_kernel,
                         cudaFuncAttributeMaxDynamicSharedMemorySize, SM_TOTAL);

    void* counts_ptr = nullptr;
    cudaGetSymbolAddress(&counts_ptr, g_counts);
    cudaMemsetAsync(counts_ptr, 0, N_NODES * sizeof(int), 0);

    hist_kernel <<<(N_EDGES + 255) / 256, 256>>>(dst);
    scanA_kernel<<<NB_SCAN, 1024>>>();
    scanC_kernel<<<NB_SCAN, 1024>>>();
    build_kernel<<<(N_EDGES + 255) / 256, 256>>>(src, dst, ppr);
    qcprep_kernel<<<F, F>>>(Qw, Qb, Ww);
    agg_kernel  <<<(N_NODES + 7) / 8, 256>>>(h);
    mmagemm_kernel<<<(N_NODES + 127) / 128, 256, SM_TOTAL>>>(h, Wb, out);
}

// round 7
// speedup vs baseline: 2.4867x; 1.0263x over previous
#include <cuda_runtime.h>
#include <cuda_bf16.h>
#include <cstdint>
#include <cstddef>

#define N_NODES 50000
#define N_EDGES 800000
#define F 128
#define KCAT 256
#define NB_SCAN 49   // ceil(50000/1024)

// ---------------------------------------------------------------------------
// Scratch (static device globals — no allocation)
// ---------------------------------------------------------------------------
__device__ int   g_counts[N_NODES];
__device__ int   g_rank[N_EDGES];                // within-dst rank of each edge
__device__ int   g_offsets[N_NODES + 1];
__device__ int   g_bsum[NB_SCAN];
__device__ int2  g_pairs[N_EDGES];               // {src, bitcast(weight)} CSR by dst
__device__ float g_aggmean[(size_t)N_NODES * F]; // segsum(w*h[src]) / wsum
__device__ float g_has[N_NODES];                 // 1 if node has incoming edges
__device__ float g_qbw[F];                       // Ww2 @ Qb
__device__ __nv_bfloat16 g_Bhi[F * KCAT];        // combined weight, bf16 hi
__device__ __nv_bfloat16 g_Blo[F * KCAT];        // combined weight, bf16 lo

// ---------------------------------------------------------------------------
// Histogram of dst + per-edge rank (x4 coarsened; N_EDGES % 4 == 0)
// ---------------------------------------------------------------------------
__global__ void hist_kernel(const int* __restrict__ dst) {
    int e0 = (blockIdx.x * blockDim.x + threadIdx.x) * 4;
    if (e0 < N_EDGES) {
        int4 d = *reinterpret_cast<const int4*>(&dst[e0]);
        int4 r;
        r.x = atomicAdd(&g_counts[d.x], 1);
        r.y = atomicAdd(&g_counts[d.y], 1);
        r.z = atomicAdd(&g_counts[d.z], 1);
        r.w = atomicAdd(&g_counts[d.w], 1);
        *reinterpret_cast<int4*>(&g_rank[e0]) = r;
    }
}

// ---------------------------------------------------------------------------
// Scan stage A: warp-shfl two-level block scan + per-block sums
// ---------------------------------------------------------------------------
__global__ __launch_bounds__(1024) void scanA_kernel() {
    __shared__ int wpart[32];
    int t = threadIdx.x;
    int lane = t & 31, wp = t >> 5;
    int i = blockIdx.x * 1024 + t;
    int v = (i < N_NODES) ? g_counts[i] : 0;
    int x = v;
#pragma unroll
    for (int o = 1; o < 32; o <<= 1) {
        int y = __shfl_up_sync(0xffffffffu, x, o);
        if (lane >= o) x += y;
    }
    if (lane == 31) wpart[wp] = x;
    __syncthreads();
    if (wp == 0) {
        int pv = wpart[lane];
        int px = pv;
#pragma unroll
        for (int o = 1; o < 32; o <<= 1) {
            int y = __shfl_up_sync(0xffffffffu, px, o);
            if (lane >= o) px += y;
        }
        wpart[lane] = px - pv;   // exclusive warp base
    }
    __syncthreads();
    int incl = x + wpart[wp];
    if (i < N_NODES) g_offsets[i] = incl - v;
    if (t == 1023) g_bsum[blockIdx.x] = incl;
}

// ---------------------------------------------------------------------------
// Scan stage C: warp 0 of every block redundantly scans the 49 block sums
// (two 32-wide shfl chunks), then all threads apply this block's prefix.
// ---------------------------------------------------------------------------
__global__ __launch_bounds__(1024) void scanC_kernel() {
    __shared__ int spref[64];
    int t = threadIdx.x;
    if (t < 32) {
        int v0 = g_bsum[t];
        int x0 = v0;
#pragma unroll
        for (int o = 1; o < 32; o <<= 1) {
            int y = __shfl_up_sync(0xffffffffu, x0, o);
            if (t >= o) x0 += y;
        }
        int tot0 = __shfl_sync(0xffffffffu, x0, 31);
        int i1 = 32 + t;
        int v1 = (i1 < NB_SCAN) ? g_bsum[i1] : 0;
        int x1 = v1;
#pragma unroll
        for (int o = 1; o < 32; o <<= 1) {
            int y = __shfl_up_sync(0xffffffffu, x1, o);
            if (t >= o) x1 += y;
        }
        spref[t] = x0 - v0;
        spref[i1] = x1 + tot0 - v1;
    }
    __syncthreads();

    int sbase = spref[blockIdx.x];
    int i = blockIdx.x * 1024 + t;
    if (i < N_NODES) g_offsets[i] += sbase;
    if (blockIdx.x == 0 && t == 0) g_offsets[N_NODES] = N_EDGES;
}

// ---------------------------------------------------------------------------
// Bucket-build: atomic-free, pos = offsets[dst] + rank[e]; x4 coarsened
// ---------------------------------------------------------------------------
__global__ void build_kernel(const int* __restrict__ src, const int* __restrict__ dst,
                             const float* __restrict__ w) {
    int e0 = (blockIdx.x * blockDim.x + threadIdx.x) * 4;
    if (e0 < N_EDGES) {
        int4   d = *reinterpret_cast<const int4*>(&dst[e0]);
        int4   s = *reinterpret_cast<const int4*>(&src[e0]);
        float4 x = *reinterpret_cast<const float4*>(&w[e0]);
        int4   r = *reinterpret_cast<const int4*>(&g_rank[e0]);
        int p0 = g_offsets[d.x] + r.x;
        int p1 = g_offsets[d.y] + r.y;
        int p2 = g_offsets[d.z] + r.z;
        int p3 = g_offsets[d.w] + r.w;
        g_pairs[p0] = make_int2(s.x, __float_as_int(x.x));
        g_pairs[p1] = make_int2(s.y, __float_as_int(x.y));
        g_pairs[p2] = make_int2(s.z, __float_as_int(x.z));
        g_pairs[p3] = make_int2(s.w, __float_as_int(x.w));
    }
}

// ---------------------------------------------------------------------------
// Fused Qc + weight prep:
//   Qc[o][t] = sum_k Ww2[o][k] Qw[k][t];  qbw[o] = sum_k Ww2[o][k] Qb[k]
//   Bhi/Blo[o][k] = split( k<F ? Ww[o][k] : Qc[o][k-F] )
// ---------------------------------------------------------------------------
__global__ __launch_bounds__(128) void qcprep_kernel(const float* __restrict__ Qw,
                                                     const float* __restrict__ Qb,
                                                     const float* __restrict__ Ww) {
    __shared__ float wrow[F];
    __shared__ float part[F];
    int o = blockIdx.x;
    int t = threadIdx.x;
    float w2 = Ww[(size_t)o * KCAT + F + t];
    wrow[t] = w2;
    part[t] = w2 * Qb[t];
    __syncthreads();
    float s = 0.0f;
#pragma unroll 8
    for (int k = 0; k < F; k++) s += wrow[k] * Qw[(size_t)k * F + t];

    float w1 = Ww[(size_t)o * KCAT + t];
    __nv_bfloat16 hi1 = __float2bfloat16(w1);
    g_Bhi[o * KCAT + t] = hi1;
    g_Blo[o * KCAT + t] = __float2bfloat16(w1 - __bfloat162float(hi1));
    __nv_bfloat16 hi2 = __float2bfloat16(s);
    g_Bhi[o * KCAT + F + t] = hi2;
    g_Blo[o * KCAT + F + t] = __float2bfloat16(s - __bfloat162float(hi2));

    if (t == 0) {
        float qb = 0.0f;
        for (int k = 0; k < F; k++) qb += part[k];
        g_qbw[o] = qb;
    }
}

// ---------------------------------------------------------------------------
// Warp-per-node aggregation: aggmean[n] = (sum_e w_e * h[src_e]) / wsum
// ---------------------------------------------------------------------------
__global__ __launch_bounds__(256) void agg_kernel(const float* __restrict__ h) {
    int warp = (blockIdx.x * blockDim.x + threadIdx.x) >> 5;
    int lane = threadIdx.x & 31;
    if (warp >= N_NODES) return;

    int j0 = g_offsets[warp];
    int j1 = g_offsets[warp + 1];

    float4 acc = make_float4(0.f, 0.f, 0.f, 0.f);
    float wsum = 0.0f;

    for (int base = j0; base < j1; base += 32) {
        int m = j1 - base; if (m > 32) m = 32;
        int2 p = (lane < m) ? g_pairs[base + lane] : make_int2(0, 0);
#pragma unroll 4
        for (int t = 0; t < m; t++) {
            int s = __shfl_sync(0xffffffffu, p.x, t);
            float we = __int_as_float(__shfl_sync(0xffffffffu, p.y, t));
            float4 v = *reinterpret_cast<const float4*>(&h[(size_t)s * F + lane * 4]);
            acc.x += we * v.x;
            acc.y += we * v.y;
            acc.z += we * v.z;
            acc.w += we * v.w;
            wsum += we;
        }
    }

    float winv = (wsum == 0.0f) ? 1.0f : 1.0f / wsum;
    acc.x *= winv; acc.y *= winv; acc.z *= winv; acc.w *= winv;
    *reinterpret_cast<float4*>(&g_aggmean[(size_t)warp * F + lane * 4]) = acc;
    if (lane == 0) g_has[warp] = (wsum != 0.0f) ? 1.0f : 0.0f;
}

// ---------------------------------------------------------------------------
// HMMA (mma.sync bf16x3) GEMM + epilogue:
//   out = l2norm(leaky(concat[h, aggmean] @ W^T + Wb + has*qbw))
// CTA tile: M=128, N=128, K=256 in 4 chunks of 64.
// ---------------------------------------------------------------------------
#define ASTRIDE 72                      // halves per row (64 + 8 pad)
#define TILE_HALVES (128 * ASTRIDE)     // 9216 halves = 18432 B
#define SM_AHI 0
#define SM_ALO (SM_AHI + TILE_HALVES * 2)
#define SM_BHI (SM_ALO + TILE_HALVES * 2)
#define SM_BLO (SM_BHI + TILE_HALVES * 2)
#define SM_TILES_END (SM_BLO + TILE_HALVES * 2)   // 73728
#define STG_STRIDE 132                  // floats per staged row
#define SM_WB  SM_TILES_END             // 512 B
#define SM_QBW (SM_WB + 512)            // 512 B
#define SM_TOTAL (SM_QBW + 512)         // 74752 B (stage reuses tile region)

__device__ __forceinline__ void mma_bf16(float& d0, float& d1, float& d2, float& d3,
                                         uint32_t a0, uint32_t a1, uint32_t a2, uint32_t a3,
                                         uint32_t b0, uint32_t b1) {
    asm volatile(
        "mma.sync.aligned.m16n8k16.row.col.f32.bf16.bf16.f32 "
        "{%0,%1,%2,%3}, {%4,%5,%6,%7}, {%8,%9}, {%0,%1,%2,%3};"
        : "+f"(d0), "+f"(d1), "+f"(d2), "+f"(d3)
        : "r"(a0), "r"(a1), "r"(a2), "r"(a3), "r"(b0), "r"(b1));
}

__global__ __launch_bounds__(256) void mmagemm_kernel(
    const float* __restrict__ h, const float* __restrict__ Wb,
    float* __restrict__ out)
{
    extern __shared__ char smem[];
    __nv_bfloat16* sAhi = (__nv_bfloat16*)(smem + SM_AHI);
    __nv_bfloat16* sAlo = (__nv_bfloat16*)(smem + SM_ALO);
    __nv_bfloat16* sBhi = (__nv_bfloat16*)(smem + SM_BHI);
    __nv_bfloat16* sBlo = (__nv_bfloat16*)(smem + SM_BLO);
    float* sStage = (float*)(smem + SM_AHI);          // reused after mainloop
    float* sWb    = (float*)(smem + SM_WB);
    float* sQbw   = (float*)(smem + SM_QBW);

    const int tid  = threadIdx.x;
    const int wid  = tid >> 5;
    const int lane = tid & 31;
    const int row0 = blockIdx.x * 128;

    if (tid < 128) {
        sWb[tid]  = Wb[tid];
        sQbw[tid] = g_qbw[tid];
    }

    // warp tile origin
    const int m0 = (wid & 1) * 64;
    const int n0 = (wid >> 1) * 32;
    const int qrow = lane >> 2;           // 0..7
    const int qcol = (lane & 3) * 2;      // 0,2,4,6

    float acc[4][4][4];
#pragma unroll
    for (int mt = 0; mt < 4; mt++)
#pragma unroll
        for (int nt = 0; nt < 4; nt++)
#pragma unroll
            for (int r = 0; r < 4; r++) acc[mt][nt][r] = 0.0f;

    // loader mapping: thread -> (row, 32-col half)
    const int ar  = tid >> 1;            // 0..127
    const int acb = (tid & 1) * 32;      // 0 or 32
    const int grow_a = row0 + ar;
    const bool valid_a = (grow_a < N_NODES);

    for (int c = 0; c < 4; c++) {
        __syncthreads();
        // ---- A tile: fp32 -> bf16 hi/lo split ----
        {
            const float* srcp = (c < 2) ? h : g_aggmean;
            const int colofs = (c & 1) * 64;
            const float* rowp = srcp + (size_t)grow_a * F + colofs + acb;
            __nv_bfloat16* dhi = &sAhi[ar * ASTRIDE + acb];
            __nv_bfloat16* dlo = &sAlo[ar * ASTRIDE + acb];
#pragma unroll
            for (int j = 0; j < 8; j++) {
                float4 x = valid_a ? *reinterpret_cast<const float4*>(rowp + j * 4)
                                   : make_float4(0.f, 0.f, 0.f, 0.f);
                __nv_bfloat16 h0 = __float2bfloat16(x.x);
                __nv_bfloat16 h1 = __float2bfloat16(x.y);
                __nv_bfloat16 h2 = __float2bfloat16(x.z);
                __nv_bfloat16 h3 = __float2bfloat16(x.w);
                __nv_bfloat162 hp0(h0, h1), hp1(h2, h3);
                __nv_bfloat162 lp0 = __floats2bfloat162_rn(x.x - __bfloat162float(h0),
                                                           x.y - __bfloat162float(h1));
                __nv_bfloat162 lp1 = __floats2bfloat162_rn(x.z - __bfloat162float(h2),
                                                           x.w - __bfloat162float(h3));
                *reinterpret_cast<uint2*>(dhi + j * 4) =
                    make_uint2(*(uint32_t*)&hp0, *(uint32_t*)&hp1);
                *reinterpret_cast<uint2*>(dlo + j * 4) =
                    make_uint2(*(uint32_t*)&lp0, *(uint32_t*)&lp1);
            }
        }
        // ---- B tile: copy precomputed bf16 hi/lo ----
        {
            const int n  = tid >> 1;
            const int kb = (tid & 1) * 32;
            const size_t gofs = (size_t)n * KCAT + c * 64 + kb;
            const int sofs = n * ASTRIDE + kb;
#pragma unroll
            for (int j = 0; j < 4; j++) {
                *reinterpret_cast<uint4*>(&sBhi[sofs + j * 8]) =
                    *reinterpret_cast<const uint4*>(&g_Bhi[gofs + j * 8]);
                *reinterpret_cast<uint4*>(&sBlo[sofs + j * 8]) =
                    *reinterpret_cast<const uint4*>(&g_Blo[gofs + j * 8]);
            }
        }
        __syncthreads();

        // ---- compute: 3 splits x 4 k-steps x 16 mma ----
#pragma unroll
        for (int s = 0; s < 3; s++) {
            const __nv_bfloat16* pA = (s == 2) ? sAlo : sAhi;
            const __nv_bfloat16* pB = (s == 1) ? sBlo : sBhi;
#pragma unroll
            for (int ks = 0; ks < 4; ks++) {
                const int k0 = ks * 16;
                uint32_t bf[4][2];
#pragma unroll
                for (int nt = 0; nt < 4; nt++) {
                    const __nv_bfloat16* bp =
                        pB + (n0 + nt * 8 + qrow) * ASTRIDE + k0 + qcol;
                    bf[nt][0] = *reinterpret_cast<const uint32_t*>(bp);
                    bf[nt][1] = *reinterpret_cast<const uint32_t*>(bp + 8);
                }
                uint32_t af[4][4];
#pragma unroll
                for (int mt = 0; mt < 4; mt++) {
                    const __nv_bfloat16* ap =
                        pA + (m0 + mt * 16 + qrow) * ASTRIDE + k0 + qcol;
                    af[mt][0] = *reinterpret_cast<const uint32_t*>(ap);
                    af[mt][1] = *reinterpret_cast<const uint32_t*>(ap + 8 * ASTRIDE);
                    af[mt][2] = *reinterpret_cast<const uint32_t*>(ap + 8);
                    af[mt][3] = *reinterpret_cast<const uint32_t*>(ap + 8 * ASTRIDE + 8);
                }
#pragma unroll
                for (int mt = 0; mt < 4; mt++)
#pragma unroll
                    for (int nt = 0; nt < 4; nt++)
                        mma_bf16(acc[mt][nt][0], acc[mt][nt][1],
                                 acc[mt][nt][2], acc[mt][nt][3],
                                 af[mt][0], af[mt][1], af[mt][2], af[mt][3],
                                 bf[nt][0], bf[nt][1]);
            }
        }
    }

    // ---- stage accumulators to smem (reuse tile region) ----
    __syncthreads();
#pragma unroll
    for (int mt = 0; mt < 4; mt++) {
        const int r = m0 + mt * 16 + qrow;
#pragma unroll
        for (int nt = 0; nt < 4; nt++) {
            const int ccol = n0 + nt * 8 + qcol;
            *reinterpret_cast<float2*>(&sStage[r * STG_STRIDE + ccol]) =
                make_float2(acc[mt][nt][0], acc[mt][nt][1]);
            *reinterpret_cast<float2*>(&sStage[(r + 8) * STG_STRIDE + ccol]) =
                make_float2(acc[mt][nt][2], acc[mt][nt][3]);
        }
    }
    __syncthreads();

    // ---- epilogue: bias + leaky + L2 norm; thread owns half a row ----
    {
        const int r = tid >> 1;
        const int cb = (tid & 1) * 64;
        const int grow = row0 + r;
        const bool valid = (grow < N_NODES);
        const float hasv = valid ? g_has[grow] : 0.0f;

        float vals[64];
        float sq = 0.0f;
#pragma unroll
        for (int j = 0; j < 16; j++) {
            float4 x = *reinterpret_cast<const float4*>(&sStage[r * STG_STRIDE + cb + j * 4]);
            float v0 = x.x + sWb[cb + j*4 + 0] + hasv * sQbw[cb + j*4 + 0];
            float v1 = x.y + sWb[cb + j*4 + 1] + hasv * sQbw[cb + j*4 + 1];
            float v2 = x.z + sWb[cb + j*4 + 2] + hasv * sQbw[cb + j*4 + 2];
            float v3 = x.w + sWb[cb + j*4 + 3] + hasv * sQbw[cb + j*4 + 3];
            v0 = (v0 > 0.0f) ? v0 : 0.01f * v0;
            v1 = (v1 > 0.0f) ? v1 : 0.01f * v1;
            v2 = (v2 > 0.0f) ? v2 : 0.01f * v2;
            v3 = (v3 > 0.0f) ? v3 : 0.01f * v3;
            vals[j*4+0] = v0; vals[j*4+1] = v1; vals[j*4+2] = v2; vals[j*4+3] = v3;
            sq += v0 * v0 + v1 * v1 + v2 * v2 + v3 * v3;
        }
        sq += __shfl_xor_sync(0xffffffffu, sq, 1);
        float nrm = sqrtf(sq);
        float inv = (nrm == 0.0f) ? 1.0f : 1.0f / nrm;

        if (valid) {
#pragma unroll
            for (int j = 0; j < 16; j++) {
                float4 o;
                o.x = vals[j*4+0] * inv;
                o.y = vals[j*4+1] * inv;
                o.z = vals[j*4+2] * inv;
                o.w = vals[j*4+3] * inv;
                *reinterpret_cast<float4*>(&out[(size_t)grow * F + cb + j * 4]) = o;
            }
        }
    }
}

// ---------------------------------------------------------------------------
// Launch
// Inputs: 0:h 1:ppr_weight 2:Qw 3:Qb 4:Ww 5:Wb 6:src 7:dst
// ---------------------------------------------------------------------------
extern "C" void kernel_launch(void* const* d_in, const int* in_sizes, int n_in,
                              void* d_out, int out_size) {
    const float* h   = (const float*)d_in[0];
    const float* ppr = (const float*)d_in[1];
    const float* Qw  = (const float*)d_in[2];
    const float* Qb  = (const float*)d_in[3];
    const float* Ww  = (const float*)d_in[4];
    const float* Wb  = (const float*)d_in[5];
    const int*   src = (const int*)d_in[6];
    const int*   dst = (const int*)d_in[7];
    float* out = (float*)d_out;

    cudaFuncSetAttribute(mmagemm_kernel,
                         cudaFuncAttributeMaxDynamicSharedMemorySize, SM_TOTAL);

    void* counts_ptr = nullptr;
    cudaGetSymbolAddress(&counts_ptr, g_counts);
    cudaMemsetAsync(counts_ptr, 0, N_NODES * sizeof(int), 0);

    const int EQ4 = N_EDGES / 4;   // 200000
    hist_kernel <<<(EQ4 + 255) / 256, 256>>>(dst);
    scanA_kernel<<<NB_SCAN, 1024>>>();
    scanC_kernel<<<NB_SCAN, 1024>>>();
    build_kernel<<<(EQ4 + 255) / 256, 256>>>(src, dst, ppr);
    qcprep_kernel<<<F, F>>>(Qw, Qb, Ww);
    agg_kernel  <<<(N_NODES + 7) / 8, 256>>>(h);
    mmagemm_kernel<<<(N_NODES + 127) / 128, 256, SM_TOTAL>>>(h, Wb, out);
}